// round 15
// baseline (speedup 1.0000x reference)
#include <cuda_runtime.h>
#include <cuda_bf16.h>
#include <stdint.h>
#include <math.h>

#define HEADS 8
#define HW 64
#define D 32
#define NTOK 4096
#define DIMX 256
#define INCDIM 768
#define MB 2
#define LDS 40   // padded smem row stride (bf16) -> conflict-free ldmatrix

// ---------------- scratch (static device globals; no allocation) -------------
__device__ float g_Q[HEADS * NTOK * D];                 // 4 MB
__device__ float g_K[HEADS * NTOK * D];                 // 4 MB
__device__ float g_V[HEADS * NTOK * D];                 // 4 MB
__device__ float g_U[(size_t)HEADS * HW * HW * D * D];  // 134 MB row-cumsum of k (x) v
__device__ float g_Kc[HEADS * HW * HW * D];             // 4 MB k integral (row, then 2D)

// split-bf16 operands (hi + lo decomposition of fp32)
__device__ __nv_bfloat16 g_xh[NTOK * DIMX], g_xl[NTOK * DIMX];         // x rows [n][k]
__device__ __nv_bfloat16 g_wh[INCDIM * DIMX], g_wl[INCDIM * DIMX];     // [n][k] = W^T (qkv)
__device__ __nv_bfloat16 g_woh[DIMX * INCDIM], g_wol[DIMX * INCDIM];   // [n][k] = wo^T
__device__ __nv_bfloat16 g_ch[(size_t)NTOK * INCDIM], g_cl[(size_t)NTOK * INCDIM]; // Cat [n][k]

// ---------------- helpers ----------------------------------------------------
__device__ __forceinline__ void mma_bf16(float4& d, uint32_t a0, uint32_t a1,
                                         uint32_t a2, uint32_t a3,
                                         uint32_t b0, uint32_t b1) {
    asm volatile(
        "mma.sync.aligned.m16n8k16.row.col.f32.bf16.bf16.f32 "
        "{%0,%1,%2,%3}, {%4,%5,%6,%7}, {%8,%9}, {%0,%1,%2,%3};"
        : "+f"(d.x), "+f"(d.y), "+f"(d.z), "+f"(d.w)
        : "r"(a0), "r"(a1), "r"(a2), "r"(a3), "r"(b0), "r"(b1));
}

__device__ __forceinline__ void ldm4(uint32_t& r0, uint32_t& r1, uint32_t& r2,
                                     uint32_t& r3, const __nv_bfloat16* p) {
    uint32_t addr = (uint32_t)__cvta_generic_to_shared(p);
    asm volatile("ldmatrix.sync.aligned.m8n8.x4.shared.b16 {%0,%1,%2,%3}, [%4];"
                 : "=r"(r0), "=r"(r1), "=r"(r2), "=r"(r3) : "r"(addr));
}

__device__ __forceinline__ void split2(float v, __nv_bfloat16& h, __nv_bfloat16& l) {
    h = __float2bfloat16(v);
    l = __float2bfloat16(v - __bfloat162float(h));
}

__device__ __forceinline__ void cp16(uint32_t s, const void* g) {
    asm volatile("cp.async.cg.shared.global [%0], [%1], 16;" :: "r"(s), "l"(g));
}
__device__ __forceinline__ void cp_commit() {
    asm volatile("cp.async.commit_group;");
}
template <int N>
__device__ __forceinline__ void cp_wait() {
    asm volatile("cp.async.wait_group %0;" :: "n"(N));
}

// ---------------- merged input split kernel ----------------------------------
// blocks [0,1024): x (float4); [1024,1792): qkv weights^T; [1792,2560): wo^T
__global__ __launch_bounds__(256) void k_split_all(const float* __restrict__ x,
                                                   const float* __restrict__ wq,
                                                   const float* __restrict__ wk,
                                                   const float* __restrict__ wv,
                                                   const float* __restrict__ wo) {
    int b = blockIdx.x;
    if (b < 1024) {
        int i = b * 256 + threadIdx.x;
        float4 v = ((const float4*)x)[i];
        int o = i * 4;
        split2(v.x, g_xh[o + 0], g_xl[o + 0]);
        split2(v.y, g_xh[o + 1], g_xl[o + 1]);
        split2(v.z, g_xh[o + 2], g_xl[o + 2]);
        split2(v.w, g_xh[o + 3], g_xl[o + 3]);
    } else if (b < 1792) {
        int o = (b - 1024) * 256 + threadIdx.x;    // o = n*256 + k, n in [0,768)
        int n = o >> 8, k = o & 255;
        const float* W = (n < 256) ? wq : (n < 512) ? wk : wv;
        float v = W[(k << 8) + (n & 255)];
        split2(v, g_wh[o], g_wl[o]);
    } else {
        int o = (b - 1792) * 256 + threadIdx.x;    // o = n*768 + k, n in [0,256)
        int n = o / INCDIM, k = o - n * INCDIM;
        float v = wo[k * DIMX + n];
        split2(v, g_woh[o], g_wol[o]);
    }
}

// ---------------- Kernel 1: QKV GEMM (split-bf16, cp.async 2-stage) + ELU ----
// C[4096 x 768] = x @ [wq|wk|wv]; BM=64, BN=64, KC=32.
__global__ __launch_bounds__(256) void k_qkv_mma() {
    __shared__ __nv_bfloat16 S[2][4 * 64 * LDS];   // per stage: Ah|Al|Bh|Bl
    const int row0 = blockIdx.x * 64;
    const int col0g = blockIdx.y * 64;     // 0..767
    const int part = col0g >> 8;
    const int tid = threadIdx.x;
    const int warp = tid >> 5, lane = tid & 31;
    const int wm = warp & 1, wn = warp >> 1;
    const int group = lane >> 2, tg = lane & 3;
    const int lr = lane & 15, lc = lane >> 4;
    const int m = tid >> 2, q = tid & 3;

    auto issue_stage = [&](int s, int k0) {
        __nv_bfloat16* Ah = S[s];
        __nv_bfloat16* Al = Ah + 64 * LDS;
        __nv_bfloat16* Bh = Al + 64 * LDS;
        __nv_bfloat16* Bl = Bh + 64 * LDS;
        uint32_t off = (uint32_t)(m * LDS + q * 8);
        cp16((uint32_t)__cvta_generic_to_shared(&Ah[off]), &g_xh[((row0 + m) << 8) + k0 + q * 8]);
        cp16((uint32_t)__cvta_generic_to_shared(&Al[off]), &g_xl[((row0 + m) << 8) + k0 + q * 8]);
        cp16((uint32_t)__cvta_generic_to_shared(&Bh[off]), &g_wh[((col0g + m) << 8) + k0 + q * 8]);
        cp16((uint32_t)__cvta_generic_to_shared(&Bl[off]), &g_wl[((col0g + m) << 8) + k0 + q * 8]);
        cp_commit();
    };

    float4 acc[2][2];
#pragma unroll
    for (int t = 0; t < 2; t++)
#pragma unroll
        for (int nt = 0; nt < 2; nt++) acc[t][nt] = make_float4(0.f, 0.f, 0.f, 0.f);

    issue_stage(0, 0);
    for (int it = 0; it < 8; it++) {
        if (it + 1 < 8) issue_stage((it + 1) & 1, (it + 1) * 32);
        if (it + 1 < 8) cp_wait<1>(); else cp_wait<0>();
        __syncthreads();
        const __nv_bfloat16* Ah = S[it & 1];
        const __nv_bfloat16* Al = Ah + 64 * LDS;
        const __nv_bfloat16* Bh = Al + 64 * LDS;
        const __nv_bfloat16* Bl = Bh + 64 * LDS;
#pragma unroll
        for (int kk = 0; kk < 32; kk += 16) {
            uint32_t ahf[2][4], alf[2][4];
#pragma unroll
            for (int t = 0; t < 2; t++) {
                ldm4(ahf[t][0], ahf[t][1], ahf[t][2], ahf[t][3],
                     &Ah[(wm * 32 + t * 16 + lr) * LDS + kk + lc * 8]);
                ldm4(alf[t][0], alf[t][1], alf[t][2], alf[t][3],
                     &Al[(wm * 32 + t * 16 + lr) * LDS + kk + lc * 8]);
            }
#pragma unroll
            for (int nt = 0; nt < 2; nt++) {
                int bi = (wn * 16 + nt * 8 + group) * LDS + kk + tg * 2;
                uint32_t bh0 = *(const uint32_t*)&Bh[bi];
                uint32_t bh1 = *(const uint32_t*)&Bh[bi + 8];
                uint32_t bl0 = *(const uint32_t*)&Bl[bi];
                uint32_t bl1 = *(const uint32_t*)&Bl[bi + 8];
#pragma unroll
                for (int t = 0; t < 2; t++) {
                    mma_bf16(acc[t][nt], ahf[t][0], ahf[t][1], ahf[t][2], ahf[t][3], bh0, bh1);
                    mma_bf16(acc[t][nt], ahf[t][0], ahf[t][1], ahf[t][2], ahf[t][3], bl0, bl1);
                    mma_bf16(acc[t][nt], alf[t][0], alf[t][1], alf[t][2], alf[t][3], bh0, bh1);
                }
            }
        }
        __syncthreads();
    }

    float* dst = (part == 0) ? g_Q : (part == 1) ? g_K : g_V;
    const int colbase = col0g & 255;
#pragma unroll
    for (int t = 0; t < 2; t++) {
#pragma unroll
        for (int nt = 0; nt < 2; nt++) {
            int row = row0 + wm * 32 + t * 16 + group;
            int colm = colbase + wn * 16 + nt * 8 + tg * 2;
            int h = colm >> 5, e = colm & 31;
            float v0 = acc[t][nt].x, v1 = acc[t][nt].y;
            float v2 = acc[t][nt].z, v3 = acc[t][nt].w;
            if (part < 2) {
                v0 = (v0 > 0.f) ? (v0 + 1.000001f) : (expf(v0) + 1e-6f);
                v1 = (v1 > 0.f) ? (v1 + 1.000001f) : (expf(v1) + 1e-6f);
                v2 = (v2 > 0.f) ? (v2 + 1.000001f) : (expf(v2) + 1e-6f);
                v3 = (v3 > 0.f) ? (v3 + 1.000001f) : (expf(v3) + 1e-6f);
            }
            float* p0 = &dst[((size_t)(h * NTOK + row)) * D + e];
            p0[0] = v0; p0[1] = v1;
            float* p1 = &dst[((size_t)(h * NTOK + row + 8)) * D + e];
            p1[0] = v2; p1[1] = v3;
        }
    }
}

// ---------------- Kernel 2: row-direction cumsums ----------------------------
__global__ __launch_bounds__(256) void k_integral() {
    const int j = blockIdx.x;
    const int h = blockIdx.y;
    __shared__ float ksh[HW * D];
    __shared__ float vsh[HW * D];
    const int tid = threadIdx.x;
#pragma unroll
    for (int r = 0; r < 8; r++) {
        int l = tid + r * 256;
        int i = l >> 5, a = l & 31;
        size_t gi = ((size_t)(h * NTOK + i * HW + j)) * D + a;
        ksh[l] = g_K[gi];
        vsh[l] = g_V[gi];
    }
    __syncthreads();
    const int a = tid >> 3;
    const int b = (tid & 7) * 4;
    float4 acc = make_float4(0.f, 0.f, 0.f, 0.f);
    float kacc = 0.f;
    for (int i = 0; i < HW; i++) {
        float kv = ksh[i * D + a];
        float4 vv = *(const float4*)&vsh[i * D + b];
        acc.x += kv * vv.x; acc.y += kv * vv.y; acc.z += kv * vv.z; acc.w += kv * vv.w;
        *(float4*)&g_U[(((size_t)(h * HW + i)) * HW + j) * (D * D) + tid * 4] = acc;
        if (tid < 32) {
            kacc += ksh[i * D + tid];
            g_Kc[((h * HW + i) * HW + j) * D + tid] = kacc;
        }
    }
}

// ---------------- Kernel 3: column scan of g_Kc -> full 2D k integral --------
__global__ __launch_bounds__(256) void k_scan() {
    const int i = blockIdx.x;
    const int h = blockIdx.y;
    __shared__ float s[HW * D];
    float* row = g_Kc + (size_t)(h * HW + i) * HW * D;
    const int tid = threadIdx.x;
#pragma unroll
    for (int r = 0; r < 8; r++) s[tid + r * 256] = row[tid + r * 256];
    __syncthreads();
    if (tid < 32) {
        float acc = 0.f;
        for (int j = 0; j < HW; j++) {
            acc += s[j * D + tid];
            s[j * D + tid] = acc;
        }
    }
    __syncthreads();
#pragma unroll
    for (int r = 0; r < 8; r++) row[tid + r * 256] = s[tid + r * 256];
}

// ---------------- Kernel 4: windowed linear attention sweep ------------------
// MB=2 staging, 4-slot prefix ring (16 KB), forced 5 blocks/SM.
// Epilogue writes window output directly as split bf16 (g_ch/g_cl).
__global__ __launch_bounds__(256, 5) void k_attn() {
    extern __shared__ float smem[];
    float* qsh   = smem;                 // 2048 floats
    float* numsh = smem + 2048;          // 2048
    float* Msh   = smem + 4096;          // 4 * 1024
    float* densh = smem + 4096 + 4096;   // 64

    const int ii = blockIdx.x;
    const int win = blockIdx.y;
    const int h = blockIdx.z;
    const int r = (win == 0) ? 32 : (win == 1) ? 16 : 8;

    const int tid = threadIdx.x;
    const int warp = tid >> 5, lane = tid & 31;

#pragma unroll
    for (int rr = 0; rr < 8; rr++) {
        int l = tid + rr * 256;
        qsh[l] = g_Q[((size_t)(h * NTOK + ii * HW)) * D + l];
        numsh[l] = 0.f;
    }

    const int x2 = min(ii + r, HW - 1);
    const int xl = ii - r - 1;
    const bool hasl = (xl >= 0);
    const float* Uh = g_U + ((size_t)(h * HW + x2)) * HW * (D * D) + tid * 4;
    const float* Ul = g_U + ((size_t)(h * HW + max(xl, 0))) * HW * (D * D) + tid * 4;

    float4 sh[MB], sl[MB];
#pragma unroll
    for (int u = 0; u < MB; u++) {
        sh[u] = *(const float4*)&Uh[(size_t)u * (D * D)];
        if (hasl) sl[u] = *(const float4*)&Ul[(size_t)u * (D * D)];
    }
    float4 mreg = make_float4(0.f, 0.f, 0.f, 0.f);
    int rot = 0;
    __syncthreads();

    for (int j0 = 0; j0 < HW; j0 += MB) {
#pragma unroll
        for (int u = 0; u < MB; u++) {
            const int j = j0 + u;
            float4 dd = sh[u];
            if (hasl) { dd.x -= sl[u].x; dd.y -= sl[u].y; dd.z -= sl[u].z; dd.w -= sl[u].w; }
            mreg.x += dd.x; mreg.y += dd.y; mreg.z += dd.z; mreg.w += dd.w;
            *(float4*)&Msh[((j & 3) << 10) + tid * 4] = mreg;
            if (j + MB < HW) {
                size_t off = (size_t)(j + MB) * (D * D);
                sh[u] = *(const float4*)&Uh[off];
                if (hasl) sl[u] = *(const float4*)&Ul[off];
            }
        }
        __syncthreads();

#pragma unroll
        for (int u = 0; u < MB; u++) {
            const int j = j0 + u;
            const int nplus = (j == HW - 1) ? (r + 1) : ((j >= r) ? 1 : 0);
            const int jjp0  = (j == HW - 1) ? (HW - 1 - r) : (j - r);
            const int hasminus = (j + r + 1 <= HW - 1) ? 1 : 0;
            const int nev = nplus + hasminus;
            const int npairs = (nev + 1) >> 1;
            const float* M = Msh + ((j & 3) << 10);
            int w0 = warp - rot; if (w0 < 0) w0 += 8;
            for (int p = w0; p < npairs; p += 8) {
                const int e0 = 2 * p, e1 = 2 * p + 1;
                const int jjA = (e0 < nplus) ? jjp0 + e0 : j + r + 1;
                const float sgnA = (e0 < nplus) ? 1.f : -1.f;
                const bool hasB = (e1 < nev);
                const int jjB = hasB ? ((e1 < nplus) ? jjp0 + e1 : j + r + 1) : jjA;
                const float sgnB = (e1 < nplus) ? 1.f : -1.f;
                const float* qA = &qsh[jjA * D];
                const float* qB = &qsh[jjB * D];
                float rA = 0.f, rB = 0.f;
#pragma unroll
                for (int a = 0; a < 32; a += 4) {
                    float4 qa = *(const float4*)&qA[a];
                    float4 qb = *(const float4*)&qB[a];
                    float m0 = M[(a + 0) * 32 + lane];
                    float m1 = M[(a + 1) * 32 + lane];
                    float m2 = M[(a + 2) * 32 + lane];
                    float m3 = M[(a + 3) * 32 + lane];
                    rA += qa.x * m0 + qa.y * m1 + qa.z * m2 + qa.w * m3;
                    rB += qb.x * m0 + qb.y * m1 + qb.z * m2 + qb.w * m3;
                }
                numsh[jjA * D + lane] += sgnA * rA;
                if (hasB) numsh[jjB * D + lane] += sgnB * rB;
            }
            rot += npairs; rot &= 7;
        }
    }
    __syncthreads();

    const float* S2 = g_Kc + (size_t)(h * HW + x2) * HW * D;
    const float* Sl = g_Kc + (size_t)(h * HW + max(xl, 0)) * HW * D;
    for (int jj = warp; jj < HW; jj += 8) {
        const int y2 = min(jj + r, HW - 1);
        const int yl = jj - r - 1;
        float v = S2[y2 * D + lane];
        if (hasl) v -= Sl[y2 * D + lane];
        if (yl >= 0) {
            v -= S2[yl * D + lane];
            if (hasl) v += Sl[yl * D + lane];
        }
        float p = qsh[jj * D + lane] * v;
#pragma unroll
        for (int off = 16; off; off >>= 1) p += __shfl_xor_sync(0xffffffffu, p, off);
        if (lane == 0) densh[jj] = p;
    }
    __syncthreads();

    // write o = num/den directly as split bf16 into g_ch/g_cl
#pragma unroll
    for (int rr = 0; rr < 8; rr++) {
        int l = tid + rr * 256;
        int jj = l >> 5, e = l & 31;
        float o = numsh[l] / (densh[jj] + 1e-6f);
        size_t idx = (size_t)(ii * HW + jj) * INCDIM + win * DIMX + h * D + e;
        split2(o, g_ch[idx], g_cl[idx]);
    }
}

// ---------------- Kernel 5: output GEMM (split-bf16, cp.async 2-stage) -------
__global__ __launch_bounds__(256) void k_out_mma(const float* __restrict__ bo,
                                                 float* __restrict__ out) {
    __shared__ __nv_bfloat16 S[2][4 * 64 * LDS];   // per stage: Ah|Al|Bh|Bl
    const int row0 = blockIdx.x * 64;
    const int col0 = blockIdx.y * 64;
    const int tid = threadIdx.x;
    const int warp = tid >> 5, lane = tid & 31;
    const int wm = warp & 1, wn = warp >> 1;
    const int group = lane >> 2, tg = lane & 3;
    const int lr = lane & 15, lc = lane >> 4;
    const int m = tid >> 2, q = tid & 3;

    auto issue_stage = [&](int s, int k0) {
        __nv_bfloat16* Ah = S[s];
        __nv_bfloat16* Al = Ah + 64 * LDS;
        __nv_bfloat16* Bh = Al + 64 * LDS;
        __nv_bfloat16* Bl = Bh + 64 * LDS;
        uint32_t off = (uint32_t)(m * LDS + q * 8);
        cp16((uint32_t)__cvta_generic_to_shared(&Ah[off]), &g_ch[(size_t)(row0 + m) * INCDIM + k0 + q * 8]);
        cp16((uint32_t)__cvta_generic_to_shared(&Al[off]), &g_cl[(size_t)(row0 + m) * INCDIM + k0 + q * 8]);
        cp16((uint32_t)__cvta_generic_to_shared(&Bh[off]), &g_woh[(size_t)(col0 + m) * INCDIM + k0 + q * 8]);
        cp16((uint32_t)__cvta_generic_to_shared(&Bl[off]), &g_wol[(size_t)(col0 + m) * INCDIM + k0 + q * 8]);
        cp_commit();
    };

    float4 acc[2][2];
#pragma unroll
    for (int t = 0; t < 2; t++)
#pragma unroll
        for (int nt = 0; nt < 2; nt++) acc[t][nt] = make_float4(0.f, 0.f, 0.f, 0.f);

    issue_stage(0, 0);
    for (int it = 0; it < 24; it++) {
        if (it + 1 < 24) issue_stage((it + 1) & 1, (it + 1) * 32);
        if (it + 1 < 24) cp_wait<1>(); else cp_wait<0>();
        __syncthreads();
        const __nv_bfloat16* Ah = S[it & 1];
        const __nv_bfloat16* Al = Ah + 64 * LDS;
        const __nv_bfloat16* Bh = Al + 64 * LDS;
        const __nv_bfloat16* Bl = Bh + 64 * LDS;
#pragma unroll
        for (int kk = 0; kk < 32; kk += 16) {
            uint32_t ahf[2][4], alf[2][4];
#pragma unroll
            for (int t = 0; t < 2; t++) {
                ldm4(ahf[t][0], ahf[t][1], ahf[t][2], ahf[t][3],
                     &Ah[(wm * 32 + t * 16 + lr) * LDS + kk + lc * 8]);
                ldm4(alf[t][0], alf[t][1], alf[t][2], alf[t][3],
                     &Al[(wm * 32 + t * 16 + lr) * LDS + kk + lc * 8]);
            }
#pragma unroll
            for (int nt = 0; nt < 2; nt++) {
                int bi = (wn * 16 + nt * 8 + group) * LDS + kk + tg * 2;
                uint32_t bh0 = *(const uint32_t*)&Bh[bi];
                uint32_t bh1 = *(const uint32_t*)&Bh[bi + 8];
                uint32_t bl0 = *(const uint32_t*)&Bl[bi];
                uint32_t bl1 = *(const uint32_t*)&Bl[bi + 8];
#pragma unroll
                for (int t = 0; t < 2; t++) {
                    mma_bf16(acc[t][nt], ahf[t][0], ahf[t][1], ahf[t][2], ahf[t][3], bh0, bh1);
                    mma_bf16(acc[t][nt], ahf[t][0], ahf[t][1], ahf[t][2], ahf[t][3], bl0, bl1);
                    mma_bf16(acc[t][nt], alf[t][0], alf[t][1], alf[t][2], alf[t][3], bh0, bh1);
                }
            }
        }
        __syncthreads();
    }

#pragma unroll
    for (int t = 0; t < 2; t++) {
#pragma unroll
        for (int nt = 0; nt < 2; nt++) {
            int row = row0 + wm * 32 + t * 16 + group;
            int col = col0 + wn * 16 + nt * 8 + tg * 2;
            float b0 = bo[col], b1 = bo[col + 1];
            float* p0 = &out[(size_t)row * DIMX + col];
            p0[0] = acc[t][nt].x + b0;
            p0[1] = acc[t][nt].y + b1;
            float* p1 = &out[(size_t)(row + 8) * DIMX + col];
            p1[0] = acc[t][nt].z + b0;
            p1[1] = acc[t][nt].w + b1;
        }
    }
}

// ---------------- launch -----------------------------------------------------
#define ATTN_SMEM ((2048 + 2048 + 4096 + 64) * 4)

extern "C" void kernel_launch(void* const* d_in, const int* in_sizes, int n_in,
                              void* d_out, int out_size) {
    const float* x  = (const float*)d_in[0];
    const float* wq = (const float*)d_in[1];
    const float* wk = (const float*)d_in[2];
    const float* wv = (const float*)d_in[3];
    const float* wo = (const float*)d_in[4];
    const float* bo = (const float*)d_in[5];
    float* out = (float*)d_out;

    cudaFuncSetAttribute(k_attn, cudaFuncAttributeMaxDynamicSharedMemorySize, ATTN_SMEM);

    k_split_all<<<2560, 256>>>(x, wq, wk, wv, wo);
    k_qkv_mma<<<dim3(NTOK / 64, INCDIM / 64), 256>>>();
    k_integral<<<dim3(HW, HEADS), 256>>>();
    k_scan<<<dim3(HW, HEADS), 256>>>();
    k_attn<<<dim3(HW, 3, HEADS), 256, ATTN_SMEM>>>();
    k_out_mma<<<dim3(NTOK / 64, DIMX / 64), 256>>>(bo, out);
}

// round 16
// speedup vs baseline: 1.0718x; 1.0718x over previous
#include <cuda_runtime.h>
#include <cuda_bf16.h>
#include <stdint.h>
#include <math.h>

#define HEADS 8
#define HW 64
#define D 32
#define NTOK 4096
#define DIMX 256
#define INCDIM 768
#define MB 2
#define LDS 40   // padded smem row stride (bf16) -> conflict-free ldmatrix

// ---------------- scratch (static device globals; no allocation) -------------
__device__ float g_Q[HEADS * NTOK * D];                 // 4 MB
__device__ float g_K[HEADS * NTOK * D];                 // 4 MB
__device__ float g_V[HEADS * NTOK * D];                 // 4 MB
__device__ float g_U[(size_t)HEADS * HW * HW * D * D];  // 134 MB row-cumsum of k (x) v
__device__ float g_Kc[HEADS * HW * HW * D];             // 4 MB k integral (row, then 2D)

// split-bf16 operands (hi + lo decomposition of fp32)
__device__ __nv_bfloat16 g_xh[NTOK * DIMX], g_xl[NTOK * DIMX];         // x rows [n][k]
__device__ __nv_bfloat16 g_wh[INCDIM * DIMX], g_wl[INCDIM * DIMX];     // [n][k] = W^T (qkv)
__device__ __nv_bfloat16 g_woh[DIMX * INCDIM], g_wol[DIMX * INCDIM];   // [n][k] = wo^T
__device__ __nv_bfloat16 g_ch[(size_t)NTOK * INCDIM], g_cl[(size_t)NTOK * INCDIM]; // Cat [n][k]

// ---------------- helpers ----------------------------------------------------
__device__ __forceinline__ void mma_bf16(float4& d, uint32_t a0, uint32_t a1,
                                         uint32_t a2, uint32_t a3,
                                         uint32_t b0, uint32_t b1) {
    asm volatile(
        "mma.sync.aligned.m16n8k16.row.col.f32.bf16.bf16.f32 "
        "{%0,%1,%2,%3}, {%4,%5,%6,%7}, {%8,%9}, {%0,%1,%2,%3};"
        : "+f"(d.x), "+f"(d.y), "+f"(d.z), "+f"(d.w)
        : "r"(a0), "r"(a1), "r"(a2), "r"(a3), "r"(b0), "r"(b1));
}

__device__ __forceinline__ void ldm4(uint32_t& r0, uint32_t& r1, uint32_t& r2,
                                     uint32_t& r3, const __nv_bfloat16* p) {
    uint32_t addr = (uint32_t)__cvta_generic_to_shared(p);
    asm volatile("ldmatrix.sync.aligned.m8n8.x4.shared.b16 {%0,%1,%2,%3}, [%4];"
                 : "=r"(r0), "=r"(r1), "=r"(r2), "=r"(r3) : "r"(addr));
}

__device__ __forceinline__ void split2(float v, __nv_bfloat16& h, __nv_bfloat16& l) {
    h = __float2bfloat16(v);
    l = __float2bfloat16(v - __bfloat162float(h));
}

__device__ __forceinline__ void cp16(uint32_t s, const void* g) {
    asm volatile("cp.async.cg.shared.global [%0], [%1], 16;" :: "r"(s), "l"(g));
}
__device__ __forceinline__ void cp_commit() {
    asm volatile("cp.async.commit_group;");
}
template <int N>
__device__ __forceinline__ void cp_wait() {
    asm volatile("cp.async.wait_group %0;" :: "n"(N));
}

// ---------------- merged input split kernel ----------------------------------
// blocks [0,1024): x (float4); [1024,1792): qkv weights^T; [1792,2560): wo^T
__global__ __launch_bounds__(256) void k_split_all(const float* __restrict__ x,
                                                   const float* __restrict__ wq,
                                                   const float* __restrict__ wk,
                                                   const float* __restrict__ wv,
                                                   const float* __restrict__ wo) {
    int b = blockIdx.x;
    if (b < 1024) {
        int i = b * 256 + threadIdx.x;
        float4 v = ((const float4*)x)[i];
        int o = i * 4;
        split2(v.x, g_xh[o + 0], g_xl[o + 0]);
        split2(v.y, g_xh[o + 1], g_xl[o + 1]);
        split2(v.z, g_xh[o + 2], g_xl[o + 2]);
        split2(v.w, g_xh[o + 3], g_xl[o + 3]);
    } else if (b < 1792) {
        int o = (b - 1024) * 256 + threadIdx.x;    // o = n*256 + k, n in [0,768)
        int n = o >> 8, k = o & 255;
        const float* W = (n < 256) ? wq : (n < 512) ? wk : wv;
        float v = W[(k << 8) + (n & 255)];
        split2(v, g_wh[o], g_wl[o]);
    } else {
        int o = (b - 1792) * 256 + threadIdx.x;    // o = n*768 + k, n in [0,256)
        int n = o / INCDIM, k = o - n * INCDIM;
        float v = wo[k * DIMX + n];
        split2(v, g_woh[o], g_wol[o]);
    }
}

// ---------------- Kernel 1: QKV GEMM (split-bf16, cp.async 3-stage) + ELU ----
// C[4096 x 768] = x @ [wq|wk|wv]; BM=64, BN=64, KC=32; 3-stage dynamic smem.
#define QKV_STG (4 * 64 * LDS)                 // bf16 per stage (Ah|Al|Bh|Bl)
#define QKV_SMEM (3 * QKV_STG * 2)             // 61440 B

__global__ __launch_bounds__(256) void k_qkv_mma() {
    extern __shared__ __nv_bfloat16 qsm[];
    const int row0 = blockIdx.x * 64;
    const int col0g = blockIdx.y * 64;     // 0..767
    const int part = col0g >> 8;
    const int tid = threadIdx.x;
    const int warp = tid >> 5, lane = tid & 31;
    const int wm = warp & 1, wn = warp >> 1;
    const int group = lane >> 2, tg = lane & 3;
    const int lr = lane & 15, lc = lane >> 4;
    const int m = tid >> 2, q = tid & 3;

    auto issue_stage = [&](int s, int k0) {
        __nv_bfloat16* Ah = qsm + s * QKV_STG;
        __nv_bfloat16* Al = Ah + 64 * LDS;
        __nv_bfloat16* Bh = Al + 64 * LDS;
        __nv_bfloat16* Bl = Bh + 64 * LDS;
        uint32_t off = (uint32_t)(m * LDS + q * 8);
        cp16((uint32_t)__cvta_generic_to_shared(&Ah[off]), &g_xh[((row0 + m) << 8) + k0 + q * 8]);
        cp16((uint32_t)__cvta_generic_to_shared(&Al[off]), &g_xl[((row0 + m) << 8) + k0 + q * 8]);
        cp16((uint32_t)__cvta_generic_to_shared(&Bh[off]), &g_wh[((col0g + m) << 8) + k0 + q * 8]);
        cp16((uint32_t)__cvta_generic_to_shared(&Bl[off]), &g_wl[((col0g + m) << 8) + k0 + q * 8]);
        cp_commit();
    };

    float4 acc[2][2];
#pragma unroll
    for (int t = 0; t < 2; t++)
#pragma unroll
        for (int nt = 0; nt < 2; nt++) acc[t][nt] = make_float4(0.f, 0.f, 0.f, 0.f);

    issue_stage(0, 0);
    issue_stage(1, 32);
    for (int it = 0; it < 8; it++) {
        if (it + 2 < 8) issue_stage((it + 2) % 3, (it + 2) * 32);
        if (it < 6) cp_wait<2>(); else if (it == 6) cp_wait<1>(); else cp_wait<0>();
        __syncthreads();
        const __nv_bfloat16* Ah = qsm + (it % 3) * QKV_STG;
        const __nv_bfloat16* Al = Ah + 64 * LDS;
        const __nv_bfloat16* Bh = Al + 64 * LDS;
        const __nv_bfloat16* Bl = Bh + 64 * LDS;
#pragma unroll
        for (int kk = 0; kk < 32; kk += 16) {
            uint32_t ahf[2][4], alf[2][4];
#pragma unroll
            for (int t = 0; t < 2; t++) {
                ldm4(ahf[t][0], ahf[t][1], ahf[t][2], ahf[t][3],
                     &Ah[(wm * 32 + t * 16 + lr) * LDS + kk + lc * 8]);
                ldm4(alf[t][0], alf[t][1], alf[t][2], alf[t][3],
                     &Al[(wm * 32 + t * 16 + lr) * LDS + kk + lc * 8]);
            }
#pragma unroll
            for (int nt = 0; nt < 2; nt++) {
                int bi = (wn * 16 + nt * 8 + group) * LDS + kk + tg * 2;
                uint32_t bh0 = *(const uint32_t*)&Bh[bi];
                uint32_t bh1 = *(const uint32_t*)&Bh[bi + 8];
                uint32_t bl0 = *(const uint32_t*)&Bl[bi];
                uint32_t bl1 = *(const uint32_t*)&Bl[bi + 8];
#pragma unroll
                for (int t = 0; t < 2; t++) {
                    mma_bf16(acc[t][nt], ahf[t][0], ahf[t][1], ahf[t][2], ahf[t][3], bh0, bh1);
                    mma_bf16(acc[t][nt], ahf[t][0], ahf[t][1], ahf[t][2], ahf[t][3], bl0, bl1);
                    mma_bf16(acc[t][nt], alf[t][0], alf[t][1], alf[t][2], alf[t][3], bh0, bh1);
                }
            }
        }
        __syncthreads();
    }

    float* dst = (part == 0) ? g_Q : (part == 1) ? g_K : g_V;
    const int colbase = col0g & 255;
#pragma unroll
    for (int t = 0; t < 2; t++) {
#pragma unroll
        for (int nt = 0; nt < 2; nt++) {
            int row = row0 + wm * 32 + t * 16 + group;
            int colm = colbase + wn * 16 + nt * 8 + tg * 2;
            int h = colm >> 5, e = colm & 31;
            float v0 = acc[t][nt].x, v1 = acc[t][nt].y;
            float v2 = acc[t][nt].z, v3 = acc[t][nt].w;
            if (part < 2) {
                v0 = (v0 > 0.f) ? (v0 + 1.000001f) : (expf(v0) + 1e-6f);
                v1 = (v1 > 0.f) ? (v1 + 1.000001f) : (expf(v1) + 1e-6f);
                v2 = (v2 > 0.f) ? (v2 + 1.000001f) : (expf(v2) + 1e-6f);
                v3 = (v3 > 0.f) ? (v3 + 1.000001f) : (expf(v3) + 1e-6f);
            }
            float* p0 = &dst[((size_t)(h * NTOK + row)) * D + e];
            p0[0] = v0; p0[1] = v1;
            float* p1 = &dst[((size_t)(h * NTOK + row + 8)) * D + e];
            p1[0] = v2; p1[1] = v3;
        }
    }
}

// ---------------- Kernel 2: row-direction cumsums ----------------------------
__global__ __launch_bounds__(256) void k_integral() {
    const int j = blockIdx.x;
    const int h = blockIdx.y;
    __shared__ float ksh[HW * D];
    __shared__ float vsh[HW * D];
    const int tid = threadIdx.x;
#pragma unroll
    for (int r = 0; r < 8; r++) {
        int l = tid + r * 256;
        int i = l >> 5, a = l & 31;
        size_t gi = ((size_t)(h * NTOK + i * HW + j)) * D + a;
        ksh[l] = g_K[gi];
        vsh[l] = g_V[gi];
    }
    __syncthreads();
    const int a = tid >> 3;
    const int b = (tid & 7) * 4;
    float4 acc = make_float4(0.f, 0.f, 0.f, 0.f);
    float kacc = 0.f;
    for (int i = 0; i < HW; i++) {
        float kv = ksh[i * D + a];
        float4 vv = *(const float4*)&vsh[i * D + b];
        acc.x += kv * vv.x; acc.y += kv * vv.y; acc.z += kv * vv.z; acc.w += kv * vv.w;
        *(float4*)&g_U[(((size_t)(h * HW + i)) * HW + j) * (D * D) + tid * 4] = acc;
        if (tid < 32) {
            kacc += ksh[i * D + tid];
            g_Kc[((h * HW + i) * HW + j) * D + tid] = kacc;
        }
    }
}

// ---------------- Kernel 3: column scan of g_Kc -> full 2D k integral --------
__global__ __launch_bounds__(256) void k_scan() {
    const int i = blockIdx.x;
    const int h = blockIdx.y;
    __shared__ float s[HW * D];
    float* row = g_Kc + (size_t)(h * HW + i) * HW * D;
    const int tid = threadIdx.x;
#pragma unroll
    for (int r = 0; r < 8; r++) s[tid + r * 256] = row[tid + r * 256];
    __syncthreads();
    if (tid < 32) {
        float acc = 0.f;
        for (int j = 0; j < HW; j++) {
            acc += s[j * D + tid];
            s[j * D + tid] = acc;
        }
    }
    __syncthreads();
#pragma unroll
    for (int r = 0; r < 8; r++) row[tid + r * 256] = s[tid + r * 256];
}

// ---------------- Kernel 4: windowed linear attention sweep (R14-proven) -----
// MB=2 staging, 8-slot prefix ring, forced 4 blocks/SM.
// Epilogue writes window output directly as split bf16 (g_ch/g_cl).
__global__ __launch_bounds__(256, 4) void k_attn() {
    extern __shared__ float smem[];
    float* qsh   = smem;                 // 2048 floats
    float* numsh = smem + 2048;          // 2048
    float* Msh   = smem + 4096;          // 8 * 1024
    float* densh = smem + 4096 + 8192;   // 64

    const int ii = blockIdx.x;
    const int win = blockIdx.y;
    const int h = blockIdx.z;
    const int r = (win == 0) ? 32 : (win == 1) ? 16 : 8;

    const int tid = threadIdx.x;
    const int warp = tid >> 5, lane = tid & 31;

#pragma unroll
    for (int rr = 0; rr < 8; rr++) {
        int l = tid + rr * 256;
        qsh[l] = g_Q[((size_t)(h * NTOK + ii * HW)) * D + l];
        numsh[l] = 0.f;
    }

    const int x2 = min(ii + r, HW - 1);
    const int xl = ii - r - 1;
    const bool hasl = (xl >= 0);
    const float* Uh = g_U + ((size_t)(h * HW + x2)) * HW * (D * D) + tid * 4;
    const float* Ul = g_U + ((size_t)(h * HW + max(xl, 0))) * HW * (D * D) + tid * 4;

    float4 sh[MB], sl[MB];
#pragma unroll
    for (int u = 0; u < MB; u++) {
        sh[u] = *(const float4*)&Uh[(size_t)u * (D * D)];
        if (hasl) sl[u] = *(const float4*)&Ul[(size_t)u * (D * D)];
    }
    float4 mreg = make_float4(0.f, 0.f, 0.f, 0.f);
    int rot = 0;
    __syncthreads();

    for (int j0 = 0; j0 < HW; j0 += MB) {
#pragma unroll
        for (int u = 0; u < MB; u++) {
            const int j = j0 + u;
            float4 dd = sh[u];
            if (hasl) { dd.x -= sl[u].x; dd.y -= sl[u].y; dd.z -= sl[u].z; dd.w -= sl[u].w; }
            mreg.x += dd.x; mreg.y += dd.y; mreg.z += dd.z; mreg.w += dd.w;
            *(float4*)&Msh[((j & 7) << 10) + tid * 4] = mreg;
            if (j + MB < HW) {
                size_t off = (size_t)(j + MB) * (D * D);
                sh[u] = *(const float4*)&Uh[off];
                if (hasl) sl[u] = *(const float4*)&Ul[off];
            }
        }
        __syncthreads();

#pragma unroll
        for (int u = 0; u < MB; u++) {
            const int j = j0 + u;
            const int nplus = (j == HW - 1) ? (r + 1) : ((j >= r) ? 1 : 0);
            const int jjp0  = (j == HW - 1) ? (HW - 1 - r) : (j - r);
            const int hasminus = (j + r + 1 <= HW - 1) ? 1 : 0;
            const int nev = nplus + hasminus;
            const int npairs = (nev + 1) >> 1;
            const float* M = Msh + ((j & 7) << 10);
            int w0 = warp - rot; if (w0 < 0) w0 += 8;
            for (int p = w0; p < npairs; p += 8) {
                const int e0 = 2 * p, e1 = 2 * p + 1;
                const int jjA = (e0 < nplus) ? jjp0 + e0 : j + r + 1;
                const float sgnA = (e0 < nplus) ? 1.f : -1.f;
                const bool hasB = (e1 < nev);
                const int jjB = hasB ? ((e1 < nplus) ? jjp0 + e1 : j + r + 1) : jjA;
                const float sgnB = (e1 < nplus) ? 1.f : -1.f;
                const float* qA = &qsh[jjA * D];
                const float* qB = &qsh[jjB * D];
                float rA = 0.f, rB = 0.f;
#pragma unroll
                for (int a = 0; a < 32; a += 4) {
                    float4 qa = *(const float4*)&qA[a];
                    float4 qb = *(const float4*)&qB[a];
                    float m0 = M[(a + 0) * 32 + lane];
                    float m1 = M[(a + 1) * 32 + lane];
                    float m2 = M[(a + 2) * 32 + lane];
                    float m3 = M[(a + 3) * 32 + lane];
                    rA += qa.x * m0 + qa.y * m1 + qa.z * m2 + qa.w * m3;
                    rB += qb.x * m0 + qb.y * m1 + qb.z * m2 + qb.w * m3;
                }
                numsh[jjA * D + lane] += sgnA * rA;
                if (hasB) numsh[jjB * D + lane] += sgnB * rB;
            }
            rot += npairs; rot &= 7;
        }
    }
    __syncthreads();

    const float* S2 = g_Kc + (size_t)(h * HW + x2) * HW * D;
    const float* Sl = g_Kc + (size_t)(h * HW + max(xl, 0)) * HW * D;
    for (int jj = warp; jj < HW; jj += 8) {
        const int y2 = min(jj + r, HW - 1);
        const int yl = jj - r - 1;
        float v = S2[y2 * D + lane];
        if (hasl) v -= Sl[y2 * D + lane];
        if (yl >= 0) {
            v -= S2[yl * D + lane];
            if (hasl) v += Sl[yl * D + lane];
        }
        float p = qsh[jj * D + lane] * v;
#pragma unroll
        for (int off = 16; off; off >>= 1) p += __shfl_xor_sync(0xffffffffu, p, off);
        if (lane == 0) densh[jj] = p;
    }
    __syncthreads();

    // write o = num/den directly as split bf16 into g_ch/g_cl
#pragma unroll
    for (int rr = 0; rr < 8; rr++) {
        int l = tid + rr * 256;
        int jj = l >> 5, e = l & 31;
        float o = numsh[l] / (densh[jj] + 1e-6f);
        size_t idx = (size_t)(ii * HW + jj) * INCDIM + win * DIMX + h * D + e;
        split2(o, g_ch[idx], g_cl[idx]);
    }
}

// ---------------- Kernel 5: output GEMM (split-bf16, cp.async 2-stage) -------
__global__ __launch_bounds__(256) void k_out_mma(const float* __restrict__ bo,
                                                 float* __restrict__ out) {
    __shared__ __nv_bfloat16 S[2][4 * 64 * LDS];   // per stage: Ah|Al|Bh|Bl
    const int row0 = blockIdx.x * 64;
    const int col0 = blockIdx.y * 64;
    const int tid = threadIdx.x;
    const int warp = tid >> 5, lane = tid & 31;
    const int wm = warp & 1, wn = warp >> 1;
    const int group = lane >> 2, tg = lane & 3;
    const int lr = lane & 15, lc = lane >> 4;
    const int m = tid >> 2, q = tid & 3;

    auto issue_stage = [&](int s, int k0) {
        __nv_bfloat16* Ah = S[s];
        __nv_bfloat16* Al = Ah + 64 * LDS;
        __nv_bfloat16* Bh = Al + 64 * LDS;
        __nv_bfloat16* Bl = Bh + 64 * LDS;
        uint32_t off = (uint32_t)(m * LDS + q * 8);
        cp16((uint32_t)__cvta_generic_to_shared(&Ah[off]), &g_ch[(size_t)(row0 + m) * INCDIM + k0 + q * 8]);
        cp16((uint32_t)__cvta_generic_to_shared(&Al[off]), &g_cl[(size_t)(row0 + m) * INCDIM + k0 + q * 8]);
        cp16((uint32_t)__cvta_generic_to_shared(&Bh[off]), &g_woh[(size_t)(col0 + m) * INCDIM + k0 + q * 8]);
        cp16((uint32_t)__cvta_generic_to_shared(&Bl[off]), &g_wol[(size_t)(col0 + m) * INCDIM + k0 + q * 8]);
        cp_commit();
    };

    float4 acc[2][2];
#pragma unroll
    for (int t = 0; t < 2; t++)
#pragma unroll
        for (int nt = 0; nt < 2; nt++) acc[t][nt] = make_float4(0.f, 0.f, 0.f, 0.f);

    issue_stage(0, 0);
    for (int it = 0; it < 24; it++) {
        if (it + 1 < 24) issue_stage((it + 1) & 1, (it + 1) * 32);
        if (it + 1 < 24) cp_wait<1>(); else cp_wait<0>();
        __syncthreads();
        const __nv_bfloat16* Ah = S[it & 1];
        const __nv_bfloat16* Al = Ah + 64 * LDS;
        const __nv_bfloat16* Bh = Al + 64 * LDS;
        const __nv_bfloat16* Bl = Bh + 64 * LDS;
#pragma unroll
        for (int kk = 0; kk < 32; kk += 16) {
            uint32_t ahf[2][4], alf[2][4];
#pragma unroll
            for (int t = 0; t < 2; t++) {
                ldm4(ahf[t][0], ahf[t][1], ahf[t][2], ahf[t][3],
                     &Ah[(wm * 32 + t * 16 + lr) * LDS + kk + lc * 8]);
                ldm4(alf[t][0], alf[t][1], alf[t][2], alf[t][3],
                     &Al[(wm * 32 + t * 16 + lr) * LDS + kk + lc * 8]);
            }
#pragma unroll
            for (int nt = 0; nt < 2; nt++) {
                int bi = (wn * 16 + nt * 8 + group) * LDS + kk + tg * 2;
                uint32_t bh0 = *(const uint32_t*)&Bh[bi];
                uint32_t bh1 = *(const uint32_t*)&Bh[bi + 8];
                uint32_t bl0 = *(const uint32_t*)&Bl[bi];
                uint32_t bl1 = *(const uint32_t*)&Bl[bi + 8];
#pragma unroll
                for (int t = 0; t < 2; t++) {
                    mma_bf16(acc[t][nt], ahf[t][0], ahf[t][1], ahf[t][2], ahf[t][3], bh0, bh1);
                    mma_bf16(acc[t][nt], ahf[t][0], ahf[t][1], ahf[t][2], ahf[t][3], bl0, bl1);
                    mma_bf16(acc[t][nt], alf[t][0], alf[t][1], alf[t][2], alf[t][3], bh0, bh1);
                }
            }
        }
        __syncthreads();
    }

#pragma unroll
    for (int t = 0; t < 2; t++) {
#pragma unroll
        for (int nt = 0; nt < 2; nt++) {
            int row = row0 + wm * 32 + t * 16 + group;
            int col = col0 + wn * 16 + nt * 8 + tg * 2;
            float b0 = bo[col], b1 = bo[col + 1];
            float* p0 = &out[(size_t)row * DIMX + col];
            p0[0] = acc[t][nt].x + b0;
            p0[1] = acc[t][nt].y + b1;
            float* p1 = &out[(size_t)(row + 8) * DIMX + col];
            p1[0] = acc[t][nt].z + b0;
            p1[1] = acc[t][nt].w + b1;
        }
    }
}

// ---------------- launch -----------------------------------------------------
#define ATTN_SMEM ((2048 + 2048 + 8192 + 64) * 4)

extern "C" void kernel_launch(void* const* d_in, const int* in_sizes, int n_in,
                              void* d_out, int out_size) {
    const float* x  = (const float*)d_in[0];
    const float* wq = (const float*)d_in[1];
    const float* wk = (const float*)d_in[2];
    const float* wv = (const float*)d_in[3];
    const float* wo = (const float*)d_in[4];
    const float* bo = (const float*)d_in[5];
    float* out = (float*)d_out;

    cudaFuncSetAttribute(k_attn, cudaFuncAttributeMaxDynamicSharedMemorySize, ATTN_SMEM);
    cudaFuncSetAttribute(k_qkv_mma, cudaFuncAttributeMaxDynamicSharedMemorySize, QKV_SMEM);

    k_split_all<<<2560, 256>>>(x, wq, wk, wv, wo);
    k_qkv_mma<<<dim3(NTOK / 64, INCDIM / 64), 256, QKV_SMEM>>>();
    k_integral<<<dim3(HW, HEADS), 256>>>();
    k_scan<<<dim3(HW, HEADS), 256>>>();
    k_attn<<<dim3(HW, 3, HEADS), 256, ATTN_SMEM>>>();
    k_out_mma<<<dim3(NTOK / 64, DIMX / 64), 256>>>(bo, out);
}

// round 17
// speedup vs baseline: 1.0728x; 1.0010x over previous
#include <cuda_runtime.h>
#include <cuda_bf16.h>
#include <stdint.h>
#include <math.h>

#define HEADS 8
#define HW 64
#define D 32
#define NTOK 4096
#define DIMX 256
#define INCDIM 768
#define MB 2
#define LDS2 72  // padded smem row stride (bf16) for KC=64 tiles -> conflict-free

// ---------------- scratch (static device globals; no allocation) -------------
__device__ float g_Q[HEADS * NTOK * D];                 // 4 MB
__device__ float g_K[HEADS * NTOK * D];                 // 4 MB
__device__ float g_V[HEADS * NTOK * D];                 // 4 MB
__device__ float g_U[(size_t)HEADS * HW * HW * D * D];  // 134 MB row-cumsum of k (x) v
__device__ float g_Kc[HEADS * HW * HW * D];             // 4 MB k integral (row, then 2D)

// split-bf16 operands (hi + lo decomposition of fp32)
__device__ __nv_bfloat16 g_xh[NTOK * DIMX], g_xl[NTOK * DIMX];         // x rows [n][k]
__device__ __nv_bfloat16 g_wh[INCDIM * DIMX], g_wl[INCDIM * DIMX];     // [n][k] = W^T (qkv)
__device__ __nv_bfloat16 g_woh[DIMX * INCDIM], g_wol[DIMX * INCDIM];   // [n][k] = wo^T
__device__ __nv_bfloat16 g_ch[(size_t)NTOK * INCDIM], g_cl[(size_t)NTOK * INCDIM]; // Cat [n][k]

// ---------------- helpers ----------------------------------------------------
__device__ __forceinline__ void mma_bf16(float4& d, uint32_t a0, uint32_t a1,
                                         uint32_t a2, uint32_t a3,
                                         uint32_t b0, uint32_t b1) {
    asm volatile(
        "mma.sync.aligned.m16n8k16.row.col.f32.bf16.bf16.f32 "
        "{%0,%1,%2,%3}, {%4,%5,%6,%7}, {%8,%9}, {%0,%1,%2,%3};"
        : "+f"(d.x), "+f"(d.y), "+f"(d.z), "+f"(d.w)
        : "r"(a0), "r"(a1), "r"(a2), "r"(a3), "r"(b0), "r"(b1));
}

__device__ __forceinline__ void ldm4(uint32_t& r0, uint32_t& r1, uint32_t& r2,
                                     uint32_t& r3, const __nv_bfloat16* p) {
    uint32_t addr = (uint32_t)__cvta_generic_to_shared(p);
    asm volatile("ldmatrix.sync.aligned.m8n8.x4.shared.b16 {%0,%1,%2,%3}, [%4];"
                 : "=r"(r0), "=r"(r1), "=r"(r2), "=r"(r3) : "r"(addr));
}

__device__ __forceinline__ void split2(float v, __nv_bfloat16& h, __nv_bfloat16& l) {
    h = __float2bfloat16(v);
    l = __float2bfloat16(v - __bfloat162float(h));
}

__device__ __forceinline__ void cp16(uint32_t s, const void* g) {
    asm volatile("cp.async.cg.shared.global [%0], [%1], 16;" :: "r"(s), "l"(g));
}
__device__ __forceinline__ void cp_commit() {
    asm volatile("cp.async.commit_group;");
}
template <int N>
__device__ __forceinline__ void cp_wait() {
    asm volatile("cp.async.wait_group %0;" :: "n"(N));
}

// ---------------- merged input split kernel ----------------------------------
// blocks [0,1024): x (float4); [1024,1792): qkv weights^T; [1792,2560): wo^T
__global__ __launch_bounds__(256) void k_split_all(const float* __restrict__ x,
                                                   const float* __restrict__ wq,
                                                   const float* __restrict__ wk,
                                                   const float* __restrict__ wv,
                                                   const float* __restrict__ wo) {
    int b = blockIdx.x;
    if (b < 1024) {
        int i = b * 256 + threadIdx.x;
        float4 v = ((const float4*)x)[i];
        int o = i * 4;
        split2(v.x, g_xh[o + 0], g_xl[o + 0]);
        split2(v.y, g_xh[o + 1], g_xl[o + 1]);
        split2(v.z, g_xh[o + 2], g_xl[o + 2]);
        split2(v.w, g_xh[o + 3], g_xl[o + 3]);
    } else if (b < 1792) {
        int o = (b - 1024) * 256 + threadIdx.x;    // o = n*256 + k, n in [0,768)
        int n = o >> 8, k = o & 255;
        const float* W = (n < 256) ? wq : (n < 512) ? wk : wv;
        float v = W[(k << 8) + (n & 255)];
        split2(v, g_wh[o], g_wl[o]);
    } else {
        int o = (b - 1792) * 256 + threadIdx.x;    // o = n*768 + k, n in [0,256)
        int n = o / INCDIM, k = o - n * INCDIM;
        float v = wo[k * DIMX + n];
        split2(v, g_woh[o], g_wol[o]);
    }
}

// ---------------- shared MMA stage compute (64x64 tile, KC=64) ---------------
// Layout per stage: Ah | Al | Bh | Bl, each 64 rows x LDS2 bf16.
#define STG_ELEMS (4 * 64 * LDS2)
#define STG_SMEM (2 * STG_ELEMS * 2)           // 2 stages in bytes (73728)

__device__ __forceinline__ void mma_compute_stage(
    const __nv_bfloat16* stg, int wm, int wn, int group, int tg, int lr, int lc,
    float4 acc[2][2]) {
    const __nv_bfloat16* Ah = stg;
    const __nv_bfloat16* Al = Ah + 64 * LDS2;
    const __nv_bfloat16* Bh = Al + 64 * LDS2;
    const __nv_bfloat16* Bl = Bh + 64 * LDS2;
#pragma unroll
    for (int kk = 0; kk < 64; kk += 16) {
        uint32_t ahf[2][4], alf[2][4];
#pragma unroll
        for (int t = 0; t < 2; t++) {
            ldm4(ahf[t][0], ahf[t][1], ahf[t][2], ahf[t][3],
                 &Ah[(wm * 32 + t * 16 + lr) * LDS2 + kk + lc * 8]);
            ldm4(alf[t][0], alf[t][1], alf[t][2], alf[t][3],
                 &Al[(wm * 32 + t * 16 + lr) * LDS2 + kk + lc * 8]);
        }
#pragma unroll
        for (int nt = 0; nt < 2; nt++) {
            int bi = (wn * 16 + nt * 8 + group) * LDS2 + kk + tg * 2;
            uint32_t bh0 = *(const uint32_t*)&Bh[bi];
            uint32_t bh1 = *(const uint32_t*)&Bh[bi + 8];
            uint32_t bl0 = *(const uint32_t*)&Bl[bi];
            uint32_t bl1 = *(const uint32_t*)&Bl[bi + 8];
#pragma unroll
            for (int t = 0; t < 2; t++) {
                mma_bf16(acc[t][nt], ahf[t][0], ahf[t][1], ahf[t][2], ahf[t][3], bh0, bh1);
                mma_bf16(acc[t][nt], ahf[t][0], ahf[t][1], ahf[t][2], ahf[t][3], bl0, bl1);
                mma_bf16(acc[t][nt], alf[t][0], alf[t][1], alf[t][2], alf[t][3], bh0, bh1);
            }
        }
    }
}

// ---------------- Kernel 1: QKV GEMM (split-bf16, KC=64, 2-stage) + ELU ------
// C[4096 x 768] = x @ [wq|wk|wv]; BM=64, BN=64, KC=64 -> 4 iterations.
__global__ __launch_bounds__(256) void k_qkv_mma() {
    extern __shared__ __nv_bfloat16 qsm[];
    const int row0 = blockIdx.x * 64;
    const int col0g = blockIdx.y * 64;     // 0..767
    const int part = col0g >> 8;
    const int tid = threadIdx.x;
    const int warp = tid >> 5, lane = tid & 31;
    const int wm = warp & 1, wn = warp >> 1;
    const int group = lane >> 2, tg = lane & 3;
    const int lr = lane & 15, lc = lane >> 4;
    const int m = tid >> 2, q = tid & 3;   // row 0..63, col quad 0..3 (16 bf16 each)

    auto issue_stage = [&](int s, int k0) {
        __nv_bfloat16* Ah = qsm + s * STG_ELEMS;
        __nv_bfloat16* Al = Ah + 64 * LDS2;
        __nv_bfloat16* Bh = Al + 64 * LDS2;
        __nv_bfloat16* Bl = Bh + 64 * LDS2;
        uint32_t off0 = (uint32_t)(m * LDS2 + q * 16);
        const int ga = ((row0 + m) << 8) + k0 + q * 16;
        const int gb = ((col0g + m) << 8) + k0 + q * 16;
        uint32_t a0 = (uint32_t)__cvta_generic_to_shared(&Ah[off0]);
        cp16(a0, &g_xh[ga]);       cp16(a0 + 16, &g_xh[ga + 8]);
        uint32_t a1 = (uint32_t)__cvta_generic_to_shared(&Al[off0]);
        cp16(a1, &g_xl[ga]);       cp16(a1 + 16, &g_xl[ga + 8]);
        uint32_t b0 = (uint32_t)__cvta_generic_to_shared(&Bh[off0]);
        cp16(b0, &g_wh[gb]);       cp16(b0 + 16, &g_wh[gb + 8]);
        uint32_t b1 = (uint32_t)__cvta_generic_to_shared(&Bl[off0]);
        cp16(b1, &g_wl[gb]);       cp16(b1 + 16, &g_wl[gb + 8]);
        cp_commit();
    };

    float4 acc[2][2];
#pragma unroll
    for (int t = 0; t < 2; t++)
#pragma unroll
        for (int nt = 0; nt < 2; nt++) acc[t][nt] = make_float4(0.f, 0.f, 0.f, 0.f);

    issue_stage(0, 0);
    for (int it = 0; it < 4; it++) {
        if (it + 1 < 4) issue_stage((it + 1) & 1, (it + 1) * 64);
        if (it + 1 < 4) cp_wait<1>(); else cp_wait<0>();
        __syncthreads();
        mma_compute_stage(qsm + (it & 1) * STG_ELEMS, wm, wn, group, tg, lr, lc, acc);
        __syncthreads();
    }

    float* dst = (part == 0) ? g_Q : (part == 1) ? g_K : g_V;
    const int colbase = col0g & 255;
#pragma unroll
    for (int t = 0; t < 2; t++) {
#pragma unroll
        for (int nt = 0; nt < 2; nt++) {
            int row = row0 + wm * 32 + t * 16 + group;
            int colm = colbase + wn * 16 + nt * 8 + tg * 2;
            int h = colm >> 5, e = colm & 31;
            float v0 = acc[t][nt].x, v1 = acc[t][nt].y;
            float v2 = acc[t][nt].z, v3 = acc[t][nt].w;
            if (part < 2) {
                v0 = (v0 > 0.f) ? (v0 + 1.000001f) : (expf(v0) + 1e-6f);
                v1 = (v1 > 0.f) ? (v1 + 1.000001f) : (expf(v1) + 1e-6f);
                v2 = (v2 > 0.f) ? (v2 + 1.000001f) : (expf(v2) + 1e-6f);
                v3 = (v3 > 0.f) ? (v3 + 1.000001f) : (expf(v3) + 1e-6f);
            }
            float* p0 = &dst[((size_t)(h * NTOK + row)) * D + e];
            p0[0] = v0; p0[1] = v1;
            float* p1 = &dst[((size_t)(h * NTOK + row + 8)) * D + e];
            p1[0] = v2; p1[1] = v3;
        }
    }
}

// ---------------- Kernel 2: row-direction cumsums ----------------------------
__global__ __launch_bounds__(256) void k_integral() {
    const int j = blockIdx.x;
    const int h = blockIdx.y;
    __shared__ float ksh[HW * D];
    __shared__ float vsh[HW * D];
    const int tid = threadIdx.x;
#pragma unroll
    for (int r = 0; r < 8; r++) {
        int l = tid + r * 256;
        int i = l >> 5, a = l & 31;
        size_t gi = ((size_t)(h * NTOK + i * HW + j)) * D + a;
        ksh[l] = g_K[gi];
        vsh[l] = g_V[gi];
    }
    __syncthreads();
    const int a = tid >> 3;
    const int b = (tid & 7) * 4;
    float4 acc = make_float4(0.f, 0.f, 0.f, 0.f);
    float kacc = 0.f;
    for (int i = 0; i < HW; i++) {
        float kv = ksh[i * D + a];
        float4 vv = *(const float4*)&vsh[i * D + b];
        acc.x += kv * vv.x; acc.y += kv * vv.y; acc.z += kv * vv.z; acc.w += kv * vv.w;
        *(float4*)&g_U[(((size_t)(h * HW + i)) * HW + j) * (D * D) + tid * 4] = acc;
        if (tid < 32) {
            kacc += ksh[i * D + tid];
            g_Kc[((h * HW + i) * HW + j) * D + tid] = kacc;
        }
    }
}

// ---------------- Kernel 3: column scan of g_Kc -> full 2D k integral --------
__global__ __launch_bounds__(256) void k_scan() {
    const int i = blockIdx.x;
    const int h = blockIdx.y;
    __shared__ float s[HW * D];
    float* row = g_Kc + (size_t)(h * HW + i) * HW * D;
    const int tid = threadIdx.x;
#pragma unroll
    for (int r = 0; r < 8; r++) s[tid + r * 256] = row[tid + r * 256];
    __syncthreads();
    if (tid < 32) {
        float acc = 0.f;
        for (int j = 0; j < HW; j++) {
            acc += s[j * D + tid];
            s[j * D + tid] = acc;
        }
    }
    __syncthreads();
#pragma unroll
    for (int r = 0; r < 8; r++) row[tid + r * 256] = s[tid + r * 256];
}

// ---------------- Kernel 4: windowed linear attention sweep (R14-proven) -----
// MB=2 staging, 8-slot prefix ring, forced 4 blocks/SM.
// Epilogue writes window output directly as split bf16 (g_ch/g_cl).
__global__ __launch_bounds__(256, 4) void k_attn() {
    extern __shared__ float smem[];
    float* qsh   = smem;                 // 2048 floats
    float* numsh = smem + 2048;          // 2048
    float* Msh   = smem + 4096;          // 8 * 1024
    float* densh = smem + 4096 + 8192;   // 64

    const int ii = blockIdx.x;
    const int win = blockIdx.y;
    const int h = blockIdx.z;
    const int r = (win == 0) ? 32 : (win == 1) ? 16 : 8;

    const int tid = threadIdx.x;
    const int warp = tid >> 5, lane = tid & 31;

#pragma unroll
    for (int rr = 0; rr < 8; rr++) {
        int l = tid + rr * 256;
        qsh[l] = g_Q[((size_t)(h * NTOK + ii * HW)) * D + l];
        numsh[l] = 0.f;
    }

    const int x2 = min(ii + r, HW - 1);
    const int xl = ii - r - 1;
    const bool hasl = (xl >= 0);
    const float* Uh = g_U + ((size_t)(h * HW + x2)) * HW * (D * D) + tid * 4;
    const float* Ul = g_U + ((size_t)(h * HW + max(xl, 0))) * HW * (D * D) + tid * 4;

    float4 sh[MB], sl[MB];
#pragma unroll
    for (int u = 0; u < MB; u++) {
        sh[u] = *(const float4*)&Uh[(size_t)u * (D * D)];
        if (hasl) sl[u] = *(const float4*)&Ul[(size_t)u * (D * D)];
    }
    float4 mreg = make_float4(0.f, 0.f, 0.f, 0.f);
    int rot = 0;
    __syncthreads();

    for (int j0 = 0; j0 < HW; j0 += MB) {
#pragma unroll
        for (int u = 0; u < MB; u++) {
            const int j = j0 + u;
            float4 dd = sh[u];
            if (hasl) { dd.x -= sl[u].x; dd.y -= sl[u].y; dd.z -= sl[u].z; dd.w -= sl[u].w; }
            mreg.x += dd.x; mreg.y += dd.y; mreg.z += dd.z; mreg.w += dd.w;
            *(float4*)&Msh[((j & 7) << 10) + tid * 4] = mreg;
            if (j + MB < HW) {
                size_t off = (size_t)(j + MB) * (D * D);
                sh[u] = *(const float4*)&Uh[off];
                if (hasl) sl[u] = *(const float4*)&Ul[off];
            }
        }
        __syncthreads();

#pragma unroll
        for (int u = 0; u < MB; u++) {
            const int j = j0 + u;
            const int nplus = (j == HW - 1) ? (r + 1) : ((j >= r) ? 1 : 0);
            const int jjp0  = (j == HW - 1) ? (HW - 1 - r) : (j - r);
            const int hasminus = (j + r + 1 <= HW - 1) ? 1 : 0;
            const int nev = nplus + hasminus;
            const int npairs = (nev + 1) >> 1;
            const float* M = Msh + ((j & 7) << 10);
            int w0 = warp - rot; if (w0 < 0) w0 += 8;
            for (int p = w0; p < npairs; p += 8) {
                const int e0 = 2 * p, e1 = 2 * p + 1;
                const int jjA = (e0 < nplus) ? jjp0 + e0 : j + r + 1;
                const float sgnA = (e0 < nplus) ? 1.f : -1.f;
                const bool hasB = (e1 < nev);
                const int jjB = hasB ? ((e1 < nplus) ? jjp0 + e1 : j + r + 1) : jjA;
                const float sgnB = (e1 < nplus) ? 1.f : -1.f;
                const float* qA = &qsh[jjA * D];
                const float* qB = &qsh[jjB * D];
                float rA = 0.f, rB = 0.f;
#pragma unroll
                for (int a = 0; a < 32; a += 4) {
                    float4 qa = *(const float4*)&qA[a];
                    float4 qb = *(const float4*)&qB[a];
                    float m0 = M[(a + 0) * 32 + lane];
                    float m1 = M[(a + 1) * 32 + lane];
                    float m2 = M[(a + 2) * 32 + lane];
                    float m3 = M[(a + 3) * 32 + lane];
                    rA += qa.x * m0 + qa.y * m1 + qa.z * m2 + qa.w * m3;
                    rB += qb.x * m0 + qb.y * m1 + qb.z * m2 + qb.w * m3;
                }
                numsh[jjA * D + lane] += sgnA * rA;
                if (hasB) numsh[jjB * D + lane] += sgnB * rB;
            }
            rot += npairs; rot &= 7;
        }
    }
    __syncthreads();

    const float* S2 = g_Kc + (size_t)(h * HW + x2) * HW * D;
    const float* Sl = g_Kc + (size_t)(h * HW + max(xl, 0)) * HW * D;
    for (int jj = warp; jj < HW; jj += 8) {
        const int y2 = min(jj + r, HW - 1);
        const int yl = jj - r - 1;
        float v = S2[y2 * D + lane];
        if (hasl) v -= Sl[y2 * D + lane];
        if (yl >= 0) {
            v -= S2[yl * D + lane];
            if (hasl) v += Sl[yl * D + lane];
        }
        float p = qsh[jj * D + lane] * v;
#pragma unroll
        for (int off = 16; off; off >>= 1) p += __shfl_xor_sync(0xffffffffu, p, off);
        if (lane == 0) densh[jj] = p;
    }
    __syncthreads();

    // write o = num/den directly as split bf16 into g_ch/g_cl
#pragma unroll
    for (int rr = 0; rr < 8; rr++) {
        int l = tid + rr * 256;
        int jj = l >> 5, e = l & 31;
        float o = numsh[l] / (densh[jj] + 1e-6f);
        size_t idx = (size_t)(ii * HW + jj) * INCDIM + win * DIMX + h * D + e;
        split2(o, g_ch[idx], g_cl[idx]);
    }
}

// ---------------- Kernel 5: output GEMM (split-bf16, KC=64, 2-stage) ---------
// out[4096 x 256] = Cat @ wo + bo; BM=64, BN=64, KC=64 -> 12 iterations.
__global__ __launch_bounds__(256) void k_out_mma(const float* __restrict__ bo,
                                                 float* __restrict__ out) {
    extern __shared__ __nv_bfloat16 osm[];
    const int row0 = blockIdx.x * 64;
    const int col0 = blockIdx.y * 64;
    const int tid = threadIdx.x;
    const int warp = tid >> 5, lane = tid & 31;
    const int wm = warp & 1, wn = warp >> 1;
    const int group = lane >> 2, tg = lane & 3;
    const int lr = lane & 15, lc = lane >> 4;
    const int m = tid >> 2, q = tid & 3;

    auto issue_stage = [&](int s, int k0) {
        __nv_bfloat16* Ah = osm + s * STG_ELEMS;
        __nv_bfloat16* Al = Ah + 64 * LDS2;
        __nv_bfloat16* Bh = Al + 64 * LDS2;
        __nv_bfloat16* Bl = Bh + 64 * LDS2;
        uint32_t off0 = (uint32_t)(m * LDS2 + q * 16);
        const size_t ga = (size_t)(row0 + m) * INCDIM + k0 + q * 16;
        const size_t gb = (size_t)(col0 + m) * INCDIM + k0 + q * 16;
        uint32_t a0 = (uint32_t)__cvta_generic_to_shared(&Ah[off0]);
        cp16(a0, &g_ch[ga]);       cp16(a0 + 16, &g_ch[ga + 8]);
        uint32_t a1 = (uint32_t)__cvta_generic_to_shared(&Al[off0]);
        cp16(a1, &g_cl[ga]);       cp16(a1 + 16, &g_cl[ga + 8]);
        uint32_t b0 = (uint32_t)__cvta_generic_to_shared(&Bh[off0]);
        cp16(b0, &g_woh[gb]);      cp16(b0 + 16, &g_woh[gb + 8]);
        uint32_t b1 = (uint32_t)__cvta_generic_to_shared(&Bl[off0]);
        cp16(b1, &g_wol[gb]);      cp16(b1 + 16, &g_wol[gb + 8]);
        cp_commit();
    };

    float4 acc[2][2];
#pragma unroll
    for (int t = 0; t < 2; t++)
#pragma unroll
        for (int nt = 0; nt < 2; nt++) acc[t][nt] = make_float4(0.f, 0.f, 0.f, 0.f);

    issue_stage(0, 0);
    for (int it = 0; it < 12; it++) {
        if (it + 1 < 12) issue_stage((it + 1) & 1, (it + 1) * 64);
        if (it + 1 < 12) cp_wait<1>(); else cp_wait<0>();
        __syncthreads();
        mma_compute_stage(osm + (it & 1) * STG_ELEMS, wm, wn, group, tg, lr, lc, acc);
        __syncthreads();
    }

#pragma unroll
    for (int t = 0; t < 2; t++) {
#pragma unroll
        for (int nt = 0; nt < 2; nt++) {
            int row = row0 + wm * 32 + t * 16 + group;
            int col = col0 + wn * 16 + nt * 8 + tg * 2;
            float b0 = bo[col], b1 = bo[col + 1];
            float* p0 = &out[(size_t)row * DIMX + col];
            p0[0] = acc[t][nt].x + b0;
            p0[1] = acc[t][nt].y + b1;
            float* p1 = &out[(size_t)(row + 8) * DIMX + col];
            p1[0] = acc[t][nt].z + b0;
            p1[1] = acc[t][nt].w + b1;
        }
    }
}

// ---------------- launch -----------------------------------------------------
#define ATTN_SMEM ((2048 + 2048 + 8192 + 64) * 4)

extern "C" void kernel_launch(void* const* d_in, const int* in_sizes, int n_in,
                              void* d_out, int out_size) {
    const float* x  = (const float*)d_in[0];
    const float* wq = (const float*)d_in[1];
    const float* wk = (const float*)d_in[2];
    const float* wv = (const float*)d_in[3];
    const float* wo = (const float*)d_in[4];
    const float* bo = (const float*)d_in[5];
    float* out = (float*)d_out;

    cudaFuncSetAttribute(k_attn, cudaFuncAttributeMaxDynamicSharedMemorySize, ATTN_SMEM);
    cudaFuncSetAttribute(k_qkv_mma, cudaFuncAttributeMaxDynamicSharedMemorySize, STG_SMEM);
    cudaFuncSetAttribute(k_out_mma, cudaFuncAttributeMaxDynamicSharedMemorySize, STG_SMEM);

    k_split_all<<<2560, 256>>>(x, wq, wk, wv, wo);
    k_qkv_mma<<<dim3(NTOK / 64, INCDIM / 64), 256, STG_SMEM>>>();
    k_integral<<<dim3(HW, HEADS), 256>>>();
    k_scan<<<dim3(HW, HEADS), 256>>>();
    k_attn<<<dim3(HW, 3, HEADS), 256, ATTN_SMEM>>>();
    k_out_mma<<<dim3(NTOK / 64, DIMX / 64), 256, STG_SMEM>>>(bo, out);
}